// round 8
// baseline (speedup 1.0000x reference)
#include <cuda_runtime.h>

#define TLEN 4096
#define DDIM 1024
#define STEPS 32

__device__ __forceinline__ float sigm(float v) { return 1.0f / (1.0f + expf(-v)); }

__global__ void __launch_bounds__(256, 4)
clifford_ring_kernel(const float* __restrict__ x,
                     const float* __restrict__ gate_w,
                     const float* __restrict__ gate_b,
                     const float* __restrict__ sw,
                     const float* __restrict__ bw,
                     float* __restrict__ out)
{
    const int l = threadIdx.x;          // lane over D/4 = 256 float4 slots
    const int q = l & 3;                // quarter within a 16-float chunk
    const int tb_per_b = TLEN / STEPS;  // 128
    const int b  = blockIdx.x / tb_per_b;
    const int t0 = (blockIdx.x % tb_per_b) * STEPS;

    const float* xb = x   + (long long)b * TLEN * DDIM + 4 * l;
    float*       ob = out + (long long)b * TLEN * DDIM + 4 * l;

    const float4 W  = __ldg((const float4*)(gate_w + 4 * l));
    const float gb0 = __ldg(gate_b);
    const float ssc = sigm(__ldg(sw));   // sigmoid(scalar_weight)
    const float sbc = sigm(__ldg(bw));   // sigmoid(bivector_weight)

    // signed-metric sign vector for the grade-0 (scalar) contraction, per quarter
    // blade idx 0..15 signs: +,+,+,-  +,-,-,-  -,+,+,+  +,+,+,-
    float4 sg;
    if      (q == 0) sg = make_float4( 1.f,  1.f,  1.f, -1.f);
    else if (q == 1) sg = make_float4( 1.f, -1.f, -1.f, -1.f);
    else if (q == 2) sg = make_float4(-1.f,  1.f,  1.f,  1.f);
    else             sg = make_float4( 1.f,  1.f,  1.f, -1.f);

    __shared__ float4 red4[2][4];        // [buf][4 x float4] = 8 x float2 (g,sc) pairs

    float4 ring[8];
    // prologue: rows t0-4 .. t0 (wrapped)
    #pragma unroll
    for (int j = -4; j <= 0; j++) {
        const int a = (t0 + j) & (TLEN - 1);
        ring[j & 7] = __ldg((const float4*)(xb + (long long)a * DDIM));
    }

    const unsigned FULL = 0xffffffffu;

    #pragma unroll
    for (int k = 1; k <= STEPS; k++) {
        // prefetch next row (one step ahead of its use)
        if (k < STEPS)
            ring[k & 7] = __ldg((const float4*)(xb + (long long)(t0 + k) * DDIM));

        const int r = t0 + k - 1;                 // row being computed
        const float4 X  = ring[(k - 1) & 7];
        const float4 M1 = ring[(k - 2) & 7];
        const float4 M2 = ring[(k - 3) & 7];
        const float4 M4 = ring[(k - 5) & 7];

        // S = x_{t-1} + x_{t-2} + x_{t-4}
        const float4 S = make_float4(M1.x + M2.x + M4.x,
                                     M1.y + M2.y + M4.y,
                                     M1.z + M2.z + M4.z,
                                     M1.w + M2.w + M4.w);

        // gate partial: x . gate_w
        float g = X.x * W.x + X.y * W.y + X.z * W.z + X.w * W.w;

        // scalar partial: sum over shifts of <x, x - x_s>_signed = <x, 3x - S>_signed
        const float4 tt = make_float4(3.f * X.x - S.x, 3.f * X.y - S.y,
                                      3.f * X.z - S.z, 3.f * X.w - S.w);
        float sc = sg.x * X.x * tt.x + sg.y * X.y * tt.y
                 + sg.z * X.z * tt.z + sg.w * X.w * tt.w;

        // wedge over shifts: x^(3x - S) = -(x^S)  => b_pq = x_q*S_p - x_p*S_q
        // vector blades within chunk: x1=q0.y, x2=q0.z, x4=q1.x, x8=q2.x
        const float x1v = __shfl_sync(FULL, X.y, 0, 4);
        const float x2v = __shfl_sync(FULL, X.z, 0, 4);
        const float x4v = __shfl_sync(FULL, X.x, 1, 4);
        const float x8v = __shfl_sync(FULL, X.x, 2, 4);
        const float S1v = __shfl_sync(FULL, S.y, 0, 4);
        const float S2v = __shfl_sync(FULL, S.z, 0, 4);
        const float S4v = __shfl_sync(FULL, S.x, 1, 4);
        const float S8v = __shfl_sync(FULL, S.x, 2, 4);

        const float b3  = x2v * S1v - x1v * S2v;   // e0^e1 -> blade 3  (q0.w)
        const float b5  = x4v * S1v - x1v * S4v;   // e0^e2 -> blade 5  (q1.y)
        const float b6  = x4v * S2v - x2v * S4v;   // e1^e2 -> blade 6  (q1.z)
        const float b9  = x8v * S1v - x1v * S8v;   // e0^e3 -> blade 9  (q2.y)
        const float b10 = x8v * S2v - x2v * S8v;   // e1^e3 -> blade 10 (q2.z)
        const float b12 = x8v * S4v - x4v * S8v;   // e2^e3 -> blade 12 (q3.x)

        // block-wide reduce of g and sc
        #pragma unroll
        for (int o = 16; o > 0; o >>= 1) {
            g  += __shfl_xor_sync(FULL, g,  o);
            sc += __shfl_xor_sync(FULL, sc, o);
        }
        const int buf = k & 1;
        if ((l & 31) == 0)
            ((float2*)&red4[buf][0])[l >> 5] = make_float2(g, sc);
        __syncthreads();
        const float4 a0 = red4[buf][0];
        const float4 a1 = red4[buf][1];
        const float4 a2 = red4[buf][2];
        const float4 a3 = red4[buf][3];
        const float G  = (a0.x + a0.z) + (a1.x + a1.z) + (a2.x + a2.z) + (a3.x + a3.z);
        const float SC = (a0.y + a0.w) + (a1.y + a1.w) + (a2.y + a2.w) + (a3.y + a3.w);

        const float gate = 1.f / (1.f + __expf(-(G + gb0)));
        const float gss  = gate * ssc;
        const float gsb  = gate * sbc;

        float4 O = X;
        O.x += (q == 3) ? gsb * b12 : ((l == 0) ? gss * SC : 0.f);
        O.y += (q == 1) ? gsb * b5  : ((q == 2) ? gsb * b9  : 0.f);
        O.z += (q == 1) ? gsb * b6  : ((q == 2) ? gsb * b10 : 0.f);
        O.w += (q == 0) ? gsb * b3  : 0.f;

        *(float4*)(ob + (long long)r * DDIM) = O;
    }
}

extern "C" void kernel_launch(void* const* d_in, const int* in_sizes, int n_in,
                              void* d_out, int out_size)
{
    const float* x  = (const float*)d_in[0];
    const float* gw = (const float*)d_in[1];
    const float* gb = (const float*)d_in[2];
    const float* sw = (const float*)d_in[3];
    const float* bw = (const float*)d_in[4];
    float* out = (float*)d_out;

    const int rows = in_sizes[0] / DDIM;        // B*T
    clifford_ring_kernel<<<rows / STEPS, 256>>>(x, gw, gb, sw, bw, out);
}